// round 15
// baseline (speedup 1.0000x reference)
#include <cuda_runtime.h>
#include <math.h>

// pyGAMNet on GB300.
// Cols 0..47: per-feature scalar MLP 1->40->20->1 (ReLU)  == scalar function f_n(x).
// Cols 48..63: class_bias[c, (int)x] gather.
//
// R15 = best-of-both recombination:
//   eval  = R14's (17.1us measured): CALL-free hot loop, 3-deep LDG pipeline,
//           contiguous conflict-free table staging from interleaved g_tabi.
//   pre   = R13's (2.96us measured): grid (48,2), 257-point chunks.

#define BSZ   131072
#define NCOL  64
#define NF    48
#define H0N   40
#define H1N   20

#define NB    512
#define XMIN  (-6.0f)
#define XMAX  (6.0f)
#define WB    (12.0f / 512.0f)        // 3/128, exact in fp32
#define SCALE (512.0f / 12.0f)
#define INVW  (512.0f / 12.0f)

#define EVAL_TPB   1024
#define EVAL_GRID  148
#define ROWS_PB    ((BSZ + EVAL_GRID - 1) / EVAL_GRID)   // 886

// smem: 12 numeric regions of (NB*4+1) float2, then 4 cat regions of (32*4+1)
#define REG_F2     (NB * 4 + 1)                   // 2049
#define CAT_REG    (32 * 4 + 1)                   // 129
#define CAT_OFF    (12 * REG_F2)                  // 24588
#define TAB_F2     (CAT_OFF + 4 * CAT_REG)        // 25104
#define SMEM_EVAL  (TAB_F2 * 8)                   // 200832 B

// global tables in the SAME interleaved layout the eval smem uses:
// g_tabi[r * 4*NB + b*4 + f]  where r = n>>2, f = n&3
__device__ float2 g_tabi[12 * 4 * NB];

// ---------------------------------------------------------------------------
// Exact fallback: full MLP eval for one (feature, x). ~Never executed.
// ---------------------------------------------------------------------------
__device__ __noinline__ float mlp_exact(
    int n, float x,
    const float* __restrict__ W0, const float* __restrict__ b0,
    const float* __restrict__ W1, const float* __restrict__ b1,
    const float* __restrict__ W2, const float* __restrict__ b2)
{
    float acc[H1N];
    for (int k = 0; k < H1N; k++) acc[k] = b1[n * H1N + k];
    for (int j = 0; j < H0N; j++) {
        const float h0 = fmaxf(fmaf(x, W0[n * H0N + j], b0[n * H0N + j]), 0.0f);
        const float* w1r = &W1[(n * H0N + j) * H1N];
        for (int k = 0; k < H1N; k++) acc[k] = fmaf(w1r[k], h0, acc[k]);
    }
    float o = b2[n];
    for (int k = 0; k < H1N; k++) o = fmaf(fmaxf(acc[k], 0.0f), W2[n * H1N + k], o);
    return o;
}

// ---------------------------------------------------------------------------
// Precompute (R13): grid (48, 2). Block (n, chunk) samples 257 grid points and
// emits 256 buckets as (m, c) lines, written directly in interleaved layout.
// ---------------------------------------------------------------------------
__global__ __launch_bounds__(256) void gam_precompute_kernel(
    const float* __restrict__ W0, const float* __restrict__ b0,
    const float* __restrict__ W1, const float* __restrict__ b1,
    const float* __restrict__ W2, const float* __restrict__ b2)
{
    __shared__ float sw0[H0N], sb0[H0N];
    __shared__ float sW1[H0N * H1N];
    __shared__ float sb1[H1N], sw2[H1N];
    __shared__ float sb2;
    __shared__ float yv[257];

    const int n  = blockIdx.x;
    const int p0 = blockIdx.y * 256;
    const int t  = threadIdx.x;

    for (int i = t; i < H0N * H1N; i += 256) sW1[i] = W1[n * H0N * H1N + i];
    if (t < H0N) {
        sw0[t] = W0[n * H0N + t];
        sb0[t] = b0[n * H0N + t];
    }
    if (t >= 64 && t < 64 + H1N) sb1[t - 64] = b1[n * H1N + (t - 64)];
    if (t >= 96 && t < 96 + H1N) sw2[t - 96] = W2[n * H1N + (t - 96)];
    if (t == 128) sb2 = b2[n];
    __syncthreads();

    for (int i = t; i < 257; i += 256) {
        const float x = fmaf((float)(p0 + i), WB, XMIN);   // exact grid point
        float acc[H1N];
        #pragma unroll
        for (int k = 0; k < H1N; k++) acc[k] = sb1[k];
        #pragma unroll 4
        for (int j = 0; j < H0N; j++) {
            const float h0 = fmaxf(fmaf(x, sw0[j], sb0[j]), 0.0f);
            const float* w1r = &sW1[j * H1N];
            #pragma unroll
            for (int k = 0; k < H1N; k++) acc[k] = fmaf(w1r[k], h0, acc[k]);
        }
        float o = sb2;
        #pragma unroll
        for (int k = 0; k < H1N; k++) o = fmaf(fmaxf(acc[k], 0.0f), sw2[k], o);
        yv[i] = o;
    }
    __syncthreads();

    {
        const int b = p0 + t;
        const float m  = (yv[t + 1] - yv[t]) * INVW;
        const float xL = fmaf((float)b, WB, XMIN);
        const float c  = fmaf(-m, xL, yv[t]);
        g_tabi[(n >> 2) * (4 * NB) + b * 4 + (n & 3)] = make_float2(m, c);
    }
}

// ---------------------------------------------------------------------------
// Eval (R14): 148 persistent blocks x 1024 threads.
// Thread -> (row = r0 + tid/16, quad q = tid%16): handles cols 4q..4q+3.
// Hot loop is CALL-free; |x|>6 handled by a cold per-thread re-walk.
// ---------------------------------------------------------------------------
struct QCtx {
    const float2* qbase;
    float scale, off, bound;
    int nbm1;
};

__device__ __forceinline__ void eval_quad_fast(
    const QCtx& ctx, const float4 v, float4& o, bool& anybad)
{
    const float xs[4] = {v.x, v.y, v.z, v.w};
    float os[4];
    #pragma unroll
    for (int f = 0; f < 4; f++) {
        const float x = xs[f];
        int b = (int)fmaf(x, ctx.scale, ctx.off);
        b = min(max(b, 0), ctx.nbm1);
        const float2 mc = ctx.qbase[b * 4 + f];
        os[f] = fmaf(mc.x, x, mc.y);
        anybad |= (fabsf(x) > ctx.bound);
    }
    o = make_float4(os[0], os[1], os[2], os[3]);
}

__global__ __launch_bounds__(EVAL_TPB, 1) void gam_eval_kernel(
    const float* __restrict__ in,
    const float* __restrict__ cb,
    const float* __restrict__ W0, const float* __restrict__ b0,
    const float* __restrict__ W1, const float* __restrict__ b1,
    const float* __restrict__ W2, const float* __restrict__ b2,
    float* __restrict__ out)
{
    extern __shared__ float smem[];
    float2* sTab = (float2*)smem;     // [TAB_F2]

    const int tid = threadIdx.x;

    // numeric tables: contiguous copy per region (coalesced, conflict-free)
    #pragma unroll
    for (int r = 0; r < 12; r++) {
        const float2* src = g_tabi + r * (4 * NB);
        float2* dst = sTab + r * REG_F2;
        dst[tid]        = src[tid];
        dst[tid + 1024] = src[tid + 1024];
    }
    // cat tables: cb[c*32+x] -> (m=0, c=bias) in region 12+(c>>2)  (tiny)
    for (int i = tid; i < 16 * 32; i += EVAL_TPB) {
        const int c = i >> 5;
        const int x = i & 31;
        sTab[CAT_OFF + (c >> 2) * CAT_REG + x * 4 + (c & 3)] =
            make_float2(0.0f, cb[i]);
    }
    __syncthreads();

    const int start = blockIdx.x * ROWS_PB;
    const int rend  = min(start + ROWS_PB, BSZ);

    const int q    = tid & 15;
    const int rrel = tid >> 4;
    const bool isnum = (q < 12);
    const int colq = q * 4;

    QCtx ctx;
    ctx.qbase = isnum ? (sTab + q * REG_F2)
                      : (sTab + CAT_OFF + (q - 12) * CAT_REG);
    ctx.scale = isnum ? SCALE : 1.0f;
    ctx.off   = isnum ? 256.0f : 0.0f;     // 6 * 512/12 = 256 exact
    ctx.bound = isnum ? XMAX : 1e30f;
    ctx.nbm1  = isnum ? (NB - 1) : 31;

    bool anybad = false;

    int r0 = start;
    // 3-deep pipelined main loop: 3 independent LDG.128 in flight
    for (; r0 + 192 <= rend; r0 += 192) {
        const int row = r0 + rrel;
        const float4 v0 = *reinterpret_cast<const float4*>(in + (row      ) * NCOL + colq);
        const float4 v1 = *reinterpret_cast<const float4*>(in + (row +  64) * NCOL + colq);
        const float4 v2 = *reinterpret_cast<const float4*>(in + (row + 128) * NCOL + colq);
        float4 o0, o1, o2;
        eval_quad_fast(ctx, v0, o0, anybad);
        eval_quad_fast(ctx, v1, o1, anybad);
        eval_quad_fast(ctx, v2, o2, anybad);
        *reinterpret_cast<float4*>(out + (row      ) * NCOL + colq) = o0;
        *reinterpret_cast<float4*>(out + (row +  64) * NCOL + colq) = o1;
        *reinterpret_cast<float4*>(out + (row + 128) * NCOL + colq) = o2;
    }
    for (; r0 + 64 <= rend; r0 += 64) {
        const int row = r0 + rrel;
        const float4 v = *reinterpret_cast<const float4*>(in + row * NCOL + colq);
        float4 o;
        eval_quad_fast(ctx, v, o, anybad);
        *reinterpret_cast<float4*>(out + row * NCOL + colq) = o;
    }
    {   // tail (< 64 rows)
        const int row = r0 + rrel;
        if (row < rend) {
            const float4 v = *reinterpret_cast<const float4*>(in + row * NCOL + colq);
            float4 o;
            eval_quad_fast(ctx, v, o, anybad);
            *reinterpret_cast<float4*>(out + row * NCOL + colq) = o;
        }
    }

    // Cold fixup: re-walk this thread's rows, exact-eval any |x|>6 element.
    if (__builtin_expect(anybad, 0)) {
        for (int rr = start; rr < rend; rr += 64) {
            const int row = rr + rrel;
            if (row < rend) {
                const float4 v = *reinterpret_cast<const float4*>(in + row * NCOL + colq);
                const float xs[4] = {v.x, v.y, v.z, v.w};
                #pragma unroll
                for (int f = 0; f < 4; f++) {
                    if (fabsf(xs[f]) > ctx.bound) {
                        out[row * NCOL + colq + f] =
                            mlp_exact(colq + f, xs[f], W0, b0, W1, b1, W2, b2);
                    }
                }
            }
        }
    }
}

extern "C" void kernel_launch(void* const* d_in, const int* in_sizes, int n_in,
                              void* d_out, int out_size)
{
    const float* in = (const float*)d_in[0];
    const float* W0 = (const float*)d_in[1];
    const float* b0 = (const float*)d_in[2];
    const float* W1 = (const float*)d_in[3];
    const float* b1 = (const float*)d_in[4];
    const float* W2 = (const float*)d_in[5];
    const float* b2 = (const float*)d_in[6];
    const float* cb = (const float*)d_in[7];
    float* out = (float*)d_out;

    static bool attr_done = false;
    if (!attr_done) {
        cudaFuncSetAttribute(gam_eval_kernel,
                             cudaFuncAttributeMaxDynamicSharedMemorySize,
                             (int)SMEM_EVAL);
        attr_done = true;
    }

    gam_precompute_kernel<<<dim3(NF, 2, 1), 256>>>(W0, b0, W1, b1, W2, b2);

    gam_eval_kernel<<<EVAL_GRID, EVAL_TPB, SMEM_EVAL>>>(
        in, cb, W0, b0, W1, b1, W2, b2, out);
}

// round 16
// speedup vs baseline: 1.0137x; 1.0137x over previous
#include <cuda_runtime.h>
#include <math.h>

// pyGAMNet on GB300.
// Cols 0..47: per-feature scalar MLP 1->40->20->1 (ReLU)  == scalar function f_n(x).
// Cols 48..63: class_bias[c, (int)x] gather.
//
// R16 = R15 (eval verified 17.1-17.6us) +
//  (1) PDL overlap: eval launched with programmatic stream serialization; its
//      g_tabi-independent prologue (cat staging, ctx setup) runs before
//      cudaGridDependencySynchronize(); precompute triggers early completion
//      right after its table writes.
//  (2) unsigned bucket clamp: umin((unsigned)b, nbm1) replaces min+max
//      (negative b -> huge unsigned -> clamps high; those lanes are |x|>6 and
//      are overwritten by the exact cold fixup).

#define BSZ   131072
#define NCOL  64
#define NF    48
#define H0N   40
#define H1N   20

#define NB    512
#define XMIN  (-6.0f)
#define XMAX  (6.0f)
#define WB    (12.0f / 512.0f)        // 3/128, exact in fp32
#define SCALE (512.0f / 12.0f)
#define INVW  (512.0f / 12.0f)

#define EVAL_TPB   1024
#define EVAL_GRID  148
#define ROWS_PB    ((BSZ + EVAL_GRID - 1) / EVAL_GRID)   // 886

// smem: 12 numeric regions of (NB*4+1) float2, then 4 cat regions of (32*4+1)
#define REG_F2     (NB * 4 + 1)                   // 2049
#define CAT_REG    (32 * 4 + 1)                   // 129
#define CAT_OFF    (12 * REG_F2)                  // 24588
#define TAB_F2     (CAT_OFF + 4 * CAT_REG)        // 25104
#define SMEM_EVAL  (TAB_F2 * 8)                   // 200832 B

// global tables in the SAME interleaved layout the eval smem uses:
// g_tabi[r * 4*NB + b*4 + f]  where r = n>>2, f = n&3
__device__ float2 g_tabi[12 * 4 * NB];

// ---------------------------------------------------------------------------
// Exact fallback: full MLP eval for one (feature, x). ~Never executed.
// ---------------------------------------------------------------------------
__device__ __noinline__ float mlp_exact(
    int n, float x,
    const float* __restrict__ W0, const float* __restrict__ b0,
    const float* __restrict__ W1, const float* __restrict__ b1,
    const float* __restrict__ W2, const float* __restrict__ b2)
{
    float acc[H1N];
    for (int k = 0; k < H1N; k++) acc[k] = b1[n * H1N + k];
    for (int j = 0; j < H0N; j++) {
        const float h0 = fmaxf(fmaf(x, W0[n * H0N + j], b0[n * H0N + j]), 0.0f);
        const float* w1r = &W1[(n * H0N + j) * H1N];
        for (int k = 0; k < H1N; k++) acc[k] = fmaf(w1r[k], h0, acc[k]);
    }
    float o = b2[n];
    for (int k = 0; k < H1N; k++) o = fmaf(fmaxf(acc[k], 0.0f), W2[n * H1N + k], o);
    return o;
}

// ---------------------------------------------------------------------------
// Precompute: grid (48, 2). Block (n, chunk) samples 257 grid points and
// emits 256 buckets as (m, c) lines, written directly in interleaved layout.
// Triggers programmatic launch completion right after its writes.
// ---------------------------------------------------------------------------
__global__ __launch_bounds__(256) void gam_precompute_kernel(
    const float* __restrict__ W0, const float* __restrict__ b0,
    const float* __restrict__ W1, const float* __restrict__ b1,
    const float* __restrict__ W2, const float* __restrict__ b2)
{
    __shared__ float sw0[H0N], sb0[H0N];
    __shared__ float sW1[H0N * H1N];
    __shared__ float sb1[H1N], sw2[H1N];
    __shared__ float sb2;
    __shared__ float yv[257];

    const int n  = blockIdx.x;
    const int p0 = blockIdx.y * 256;
    const int t  = threadIdx.x;

    for (int i = t; i < H0N * H1N; i += 256) sW1[i] = W1[n * H0N * H1N + i];
    if (t < H0N) {
        sw0[t] = W0[n * H0N + t];
        sb0[t] = b0[n * H0N + t];
    }
    if (t >= 64 && t < 64 + H1N) sb1[t - 64] = b1[n * H1N + (t - 64)];
    if (t >= 96 && t < 96 + H1N) sw2[t - 96] = W2[n * H1N + (t - 96)];
    if (t == 128) sb2 = b2[n];
    __syncthreads();

    for (int i = t; i < 257; i += 256) {
        const float x = fmaf((float)(p0 + i), WB, XMIN);   // exact grid point
        float acc[H1N];
        #pragma unroll
        for (int k = 0; k < H1N; k++) acc[k] = sb1[k];
        #pragma unroll 4
        for (int j = 0; j < H0N; j++) {
            const float h0 = fmaxf(fmaf(x, sw0[j], sb0[j]), 0.0f);
            const float* w1r = &sW1[j * H1N];
            #pragma unroll
            for (int k = 0; k < H1N; k++) acc[k] = fmaf(w1r[k], h0, acc[k]);
        }
        float o = sb2;
        #pragma unroll
        for (int k = 0; k < H1N; k++) o = fmaf(fmaxf(acc[k], 0.0f), sw2[k], o);
        yv[i] = o;
    }
    __syncthreads();

    {
        const int b = p0 + t;
        const float m  = (yv[t + 1] - yv[t]) * INVW;
        const float xL = fmaf((float)b, WB, XMIN);
        const float c  = fmaf(-m, xL, yv[t]);
        g_tabi[(n >> 2) * (4 * NB) + b * 4 + (n & 3)] = make_float2(m, c);
    }

#if __CUDA_ARCH__ >= 900
    cudaTriggerProgrammaticLaunchCompletion();
#endif
}

// ---------------------------------------------------------------------------
// Eval: 148 persistent blocks x 1024 threads.
// Thread -> (row = r0 + tid/16, quad q = tid%16): handles cols 4q..4q+3.
// Prologue independent of g_tabi runs BEFORE cudaGridDependencySynchronize().
// ---------------------------------------------------------------------------
struct QCtx {
    const float2* qbase;
    float scale, off, bound;
    unsigned nbm1;
};

__device__ __forceinline__ void eval_quad_fast(
    const QCtx& ctx, const float4 v, float4& o, bool& anybad)
{
    const float xs[4] = {v.x, v.y, v.z, v.w};
    float os[4];
    #pragma unroll
    for (int f = 0; f < 4; f++) {
        const float x = xs[f];
        const int bi = (int)fmaf(x, ctx.scale, ctx.off);
        const unsigned b = min((unsigned)bi, ctx.nbm1);   // neg -> huge -> clamps
        const float2 mc = ctx.qbase[b * 4 + f];
        os[f] = fmaf(mc.x, x, mc.y);
        anybad |= (fabsf(x) > ctx.bound);
    }
    o = make_float4(os[0], os[1], os[2], os[3]);
}

__global__ __launch_bounds__(EVAL_TPB, 1) void gam_eval_kernel(
    const float* __restrict__ in,
    const float* __restrict__ cb,
    const float* __restrict__ W0, const float* __restrict__ b0,
    const float* __restrict__ W1, const float* __restrict__ b1,
    const float* __restrict__ W2, const float* __restrict__ b2,
    float* __restrict__ out)
{
    extern __shared__ float smem[];
    float2* sTab = (float2*)smem;     // [TAB_F2]

    const int tid = threadIdx.x;

    // ---- g_tabi-INDEPENDENT prologue (overlaps primary kernel via PDL) ----
    // cat tables: cb[c*32+x] -> (m=0, c=bias) in region 12+(c>>2)
    for (int i = tid; i < 16 * 32; i += EVAL_TPB) {
        const int c = i >> 5;
        const int x = i & 31;
        sTab[CAT_OFF + (c >> 2) * CAT_REG + x * 4 + (c & 3)] =
            make_float2(0.0f, cb[i]);
    }

    const int start = blockIdx.x * ROWS_PB;
    const int rend  = min(start + ROWS_PB, BSZ);

    const int q    = tid & 15;
    const int rrel = tid >> 4;
    const bool isnum = (q < 12);
    const int colq = q * 4;

    QCtx ctx;
    ctx.qbase = isnum ? (sTab + q * REG_F2)
                      : (sTab + CAT_OFF + (q - 12) * CAT_REG);
    ctx.scale = isnum ? SCALE : 1.0f;
    ctx.off   = isnum ? 256.0f : 0.0f;     // 6 * 512/12 = 256 exact
    ctx.bound = isnum ? XMAX : 1e30f;
    ctx.nbm1  = isnum ? (NB - 1) : 31;

    // ---- wait for precompute's g_tabi writes, then stage numeric tables ----
#if __CUDA_ARCH__ >= 900
    cudaGridDependencySynchronize();
#endif
    #pragma unroll
    for (int r = 0; r < 12; r++) {
        const float2* src = g_tabi + r * (4 * NB);
        float2* dst = sTab + r * REG_F2;
        dst[tid]        = src[tid];
        dst[tid + 1024] = src[tid + 1024];
    }
    __syncthreads();

    bool anybad = false;

    int r0 = start;
    // 3-deep pipelined main loop: 3 independent LDG.128 in flight
    for (; r0 + 192 <= rend; r0 += 192) {
        const int row = r0 + rrel;
        const float4 v0 = *reinterpret_cast<const float4*>(in + (row      ) * NCOL + colq);
        const float4 v1 = *reinterpret_cast<const float4*>(in + (row +  64) * NCOL + colq);
        const float4 v2 = *reinterpret_cast<const float4*>(in + (row + 128) * NCOL + colq);
        float4 o0, o1, o2;
        eval_quad_fast(ctx, v0, o0, anybad);
        eval_quad_fast(ctx, v1, o1, anybad);
        eval_quad_fast(ctx, v2, o2, anybad);
        *reinterpret_cast<float4*>(out + (row      ) * NCOL + colq) = o0;
        *reinterpret_cast<float4*>(out + (row +  64) * NCOL + colq) = o1;
        *reinterpret_cast<float4*>(out + (row + 128) * NCOL + colq) = o2;
    }
    for (; r0 + 64 <= rend; r0 += 64) {
        const int row = r0 + rrel;
        const float4 v = *reinterpret_cast<const float4*>(in + row * NCOL + colq);
        float4 o;
        eval_quad_fast(ctx, v, o, anybad);
        *reinterpret_cast<float4*>(out + row * NCOL + colq) = o;
    }
    {   // tail (< 64 rows)
        const int row = r0 + rrel;
        if (row < rend) {
            const float4 v = *reinterpret_cast<const float4*>(in + row * NCOL + colq);
            float4 o;
            eval_quad_fast(ctx, v, o, anybad);
            *reinterpret_cast<float4*>(out + row * NCOL + colq) = o;
        }
    }

    // Cold fixup: re-walk this thread's rows, exact-eval any |x|>6 element.
    if (__builtin_expect(anybad, 0)) {
        for (int rr = start; rr < rend; rr += 64) {
            const int row = rr + rrel;
            if (row < rend) {
                const float4 v = *reinterpret_cast<const float4*>(in + row * NCOL + colq);
                const float xs[4] = {v.x, v.y, v.z, v.w};
                #pragma unroll
                for (int f = 0; f < 4; f++) {
                    if (fabsf(xs[f]) > ctx.bound) {
                        out[row * NCOL + colq + f] =
                            mlp_exact(colq + f, xs[f], W0, b0, W1, b1, W2, b2);
                    }
                }
            }
        }
    }
}

extern "C" void kernel_launch(void* const* d_in, const int* in_sizes, int n_in,
                              void* d_out, int out_size)
{
    const float* in = (const float*)d_in[0];
    const float* W0 = (const float*)d_in[1];
    const float* b0 = (const float*)d_in[2];
    const float* W1 = (const float*)d_in[3];
    const float* b1 = (const float*)d_in[4];
    const float* W2 = (const float*)d_in[5];
    const float* b2 = (const float*)d_in[6];
    const float* cb = (const float*)d_in[7];
    float* out = (float*)d_out;

    static bool attr_done = false;
    if (!attr_done) {
        cudaFuncSetAttribute(gam_eval_kernel,
                             cudaFuncAttributeMaxDynamicSharedMemorySize,
                             (int)SMEM_EVAL);
        attr_done = true;
    }

    gam_precompute_kernel<<<dim3(NF, 2, 1), 256>>>(W0, b0, W1, b1, W2, b2);

    // Eval launched with programmatic stream serialization (PDL): it may begin
    // its g_tabi-independent prologue while precompute drains.
    cudaLaunchConfig_t cfg = {};
    cfg.gridDim  = dim3(EVAL_GRID, 1, 1);
    cfg.blockDim = dim3(EVAL_TPB, 1, 1);
    cfg.dynamicSmemBytes = SMEM_EVAL;
    cudaLaunchAttribute attrs[1];
    attrs[0].id = cudaLaunchAttributeProgrammaticStreamSerialization;
    attrs[0].val.programmaticStreamSerializationAllowed = 1;
    cfg.attrs = attrs;
    cfg.numAttrs = 1;
    cudaLaunchKernelEx(&cfg, gam_eval_kernel,
                       in, cb, W0, b0, W1, b1, W2, b2, out);
}